// round 9
// baseline (speedup 1.0000x reference)
#include <cuda_runtime.h>
#include <cuda_bf16.h>
#include <cuda_fp16.h>
#include <math.h>
#include <stdint.h>

#define BATCH   32768
#define D_IN    512
#define D_DENSE 256
#define TSTEPS  16
#define FEAT    16
#define H1      128
#define H2      32
#define NCLS    10

// ---------------- state: COLUMN-major [feature][BATCH], fp16 hi/lo pairs ----------------
__device__ __half g_acthi[D_DENSE * BATCH], g_actlo[D_DENSE * BATCH];
__device__ __half g_h1hi[2][H1 * BATCH],    g_h1lo[2][H1 * BATCH];
__device__ __half g_h2hi[2][H2 * BATCH],    g_h2lo[2][H2 * BATCH];
__device__ float g_c1[H1 * BATCH], g_c2[H2 * BATCH];

// prepacked LSTM weights: single fp16, row n (gate-interleaved), K cols
__device__ __half g_Wp1[(4 * H1) * (FEAT + H1)];   // [512][144]
__device__ __half g_Wp2[(4 * H2) * (H1 + H2)];     // [128][160]
// dense1 weights stay bf16 3-term (verified engine)
__device__ __nv_bfloat16 g_WpD[D_DENSE * 2 * D_IN];  // [256][1024], panel-major
__device__ float g_bc1[4 * H1], g_bc2[4 * H2];
__device__ float g_d1sc[D_DENSE], g_d1sh[D_DENSE];

// ---------------- helpers ----------------
__device__ __forceinline__ uint32_t smem_u32(const void* p) {
    uint32_t a;
    asm("{ .reg .u64 t; cvta.to.shared.u64 t, %1; cvt.u32.u64 %0, t; }" : "=r"(a) : "l"(p));
    return a;
}
__device__ __forceinline__ float ftanh(float x) {
    float y;
    asm("tanh.approx.f32 %0, %1;" : "=f"(y) : "f"(x));
    return y;
}
__device__ __forceinline__ float fsigm(float x) { return 0.5f * ftanh(0.5f * x) + 0.5f; }

__device__ __forceinline__ void ldsm4(uint32_t* r, uint32_t addr) {
    asm volatile("ldmatrix.sync.aligned.m8n8.x4.shared.b16 {%0,%1,%2,%3}, [%4];"
                 : "=r"(r[0]), "=r"(r[1]), "=r"(r[2]), "=r"(r[3]) : "r"(addr));
}
__device__ __forceinline__ void ldsm4t(uint32_t* r, uint32_t addr) {
    asm volatile("ldmatrix.sync.aligned.m8n8.x4.trans.shared.b16 {%0,%1,%2,%3}, [%4];"
                 : "=r"(r[0]), "=r"(r[1]), "=r"(r[2]), "=r"(r[3]) : "r"(addr));
}
__device__ __forceinline__ void mma16816bf(float* d, const uint32_t* a, uint32_t b0, uint32_t b1) {
    asm volatile(
        "mma.sync.aligned.m16n8k16.row.col.f32.bf16.bf16.f32 "
        "{%0,%1,%2,%3}, {%4,%5,%6,%7}, {%8,%9}, {%0,%1,%2,%3};"
        : "+f"(d[0]), "+f"(d[1]), "+f"(d[2]), "+f"(d[3])
        : "r"(a[0]), "r"(a[1]), "r"(a[2]), "r"(a[3]), "r"(b0), "r"(b1));
}
__device__ __forceinline__ void mma16816h(float* d, const uint32_t* a, uint32_t b0, uint32_t b1) {
    asm volatile(
        "mma.sync.aligned.m16n8k16.row.col.f32.f16.f16.f32 "
        "{%0,%1,%2,%3}, {%4,%5,%6,%7}, {%8,%9}, {%0,%1,%2,%3};"
        : "+f"(d[0]), "+f"(d[1]), "+f"(d[2]), "+f"(d[3])
        : "r"(a[0]), "r"(a[1]), "r"(a[2]), "r"(a[3]), "r"(b0), "r"(b1));
}
__device__ __forceinline__ void cp16(uint32_t dst, const void* src) {
    asm volatile("cp.async.cg.shared.global [%0], [%1], 16;" :: "r"(dst), "l"(src));
}
#define CP_COMMIT() asm volatile("cp.async.commit_group;" ::: "memory")
#define CP_WAIT(n)  asm volatile("cp.async.wait_group %0;" :: "n"(n) : "memory")

// ===== fused LSTM step: fp16 2-term (Ah@B + Al@B), resident single-fp16 B, col-major state
// 256 threads, 8 warps 4(M)x2(N), warp tile 32x64, CTA tile 128x128.
template <int KX, int HID, int BK>
__device__ __forceinline__ void lstm_body(int t, int m0, int n0, char* smemc) {
    constexpr int K = KX + HID;
    constexpr int SROW = 136;                // A smem: elems per k-row (272B, conflict-free)
    constexpr int STG_A = BK * SROW * 2;
    constexpr int SB = K + 8;                // B row length in halfs (stride/16B odd)
    constexpr int CPT = K / BK;
    constexpr int NCH = 2 * CPT;             // hi chunks then lo chunks
    constexpr int GB = K / 8;
    const int tid = threadIdx.x;
    const int lane = tid & 31, wid = tid >> 5;
    const int wm = wid & 3, wn = wid >> 2;   // 4 x 2
    const uint32_t sbase = smem_u32(smemc);
    const uint32_t Bbase = sbase + 2 * STG_A;
    const int p = t & 1;

    const __half *xhi, *xlo, *hhi, *hlo;
    __half *hdhi, *hdlo;
    float* cbuf;
    const __half* W;
    const float* bias;
    int xoff;
    if (HID == H1) {
        xhi = g_acthi; xlo = g_actlo; xoff = t * FEAT;
        hhi = g_h1hi[p]; hlo = g_h1lo[p];
        hdhi = g_h1hi[p ^ 1]; hdlo = g_h1lo[p ^ 1];
        cbuf = g_c1; W = g_Wp1; bias = g_bc1;
    } else {
        xhi = g_h1hi[p ^ 1]; xlo = g_h1lo[p ^ 1]; xoff = 0;
        hhi = g_h2hi[p]; hlo = g_h2lo[p];
        hdhi = g_h2hi[p ^ 1]; hdlo = g_h2lo[p ^ 1];
        cbuf = g_c2; W = g_Wp2; bias = g_bc2;
    }

    // A loader: per k-column, 16x 16B contiguous copies from col-major state
    auto load_a = [&](int c) {
        const bool hi = c < CPT;
        const int kbase = (hi ? c : c - CPT) * BK;
        const __half* xa = hi ? xhi : xlo;
        const __half* ha = hi ? hhi : hlo;
        const uint32_t As = sbase + (uint32_t)(c & 1) * STG_A;
#pragma unroll
        for (int task = tid; task < BK * 16; task += 256) {
            const int k = task >> 4, mg = task & 15;
            const int col = kbase + k;
            const __half* src = (col < KX)
                ? xa + (size_t)(xoff + col) * BATCH + m0 + mg * 8
                : ha + (size_t)(col - KX) * BATCH + m0 + mg * 8;
            cp16(As + (uint32_t)(k * SROW + mg * 8) * 2, src);
        }
    };

    // prologue: resident B (single fp16) + first A chunk
#pragma unroll
    for (int task = tid; task < 128 * GB; task += 256) {
        const int n = task / GB, gg = task % GB;
        cp16(Bbase + (uint32_t)(n * SB + gg * 8) * 2,
             W + (size_t)(n0 + n) * K + gg * 8);
    }
    load_a(0);
    CP_COMMIT();

    const uint32_t arow = (uint32_t)((lane & 7) + ((lane >> 4) << 3));
    const uint32_t acol = (uint32_t)(wm * 32 + (((lane >> 3) & 1) << 3));
    const uint32_t brow = (uint32_t)(wn * 64 + ((lane >> 4) << 3) + (lane & 7));
    const uint32_t bcol8 = (uint32_t)(((lane >> 3) & 1) << 3);
    float acc[2][8][4] = {};

#pragma unroll 1
    for (int c = 0; c < NCH; c++) {
        CP_WAIT(0);
        __syncthreads();
        if (c + 1 < NCH) { load_a(c + 1); CP_COMMIT(); }
        const bool hi = c < CPT;
        const int kbase = (hi ? c : c - CPT) * BK;
        const uint32_t As = sbase + (uint32_t)(c & 1) * STG_A;
#pragma unroll
        for (int kk = 0; kk < BK / 16; kk++) {
            uint32_t a0[4], a1[4];
            ldsm4t(a0, As + ((kk * 16 + arow) * SROW + acol) * 2);
            ldsm4t(a1, As + ((kk * 16 + arow) * SROW + acol + 16) * 2);
            const uint32_t cofs = (uint32_t)(kbase + kk * 16) + bcol8;
#pragma unroll
            for (int nj = 0; nj < 4; nj++) {
                uint32_t b[4];
                ldsm4(b, Bbase + ((brow + nj * 16) * SB + cofs) * 2);
                mma16816h(acc[0][2 * nj], a0, b[0], b[1]);
                mma16816h(acc[0][2 * nj + 1], a0, b[2], b[3]);
                mma16816h(acc[1][2 * nj], a1, b[0], b[1]);
                mma16816h(acc[1][2 * nj + 1], a1, b[2], b[3]);
            }
        }
    }

    // epilogue: pair-swap gates; col-major state -> coalesced stores
    const int g = lane >> 2;
    const bool odd = lane & 1;
#pragma unroll
    for (int ni = 0; ni < 8; ni++) {
        const int u = ((n0 + wn * 64 + ni * 8) >> 2) + ((lane & 2) >> 1);
        const float4 bb = *(const float4*)(bias + 4 * u);
#pragma unroll
        for (int mi = 0; mi < 2; mi++) {
            const float d0 = acc[mi][ni][0], d1 = acc[mi][ni][1];
            const float d2 = acc[mi][ni][2], d3 = acc[mi][ni][3];
            const float s0 = __shfl_xor_sync(0xffffffffu, odd ? d0 : d2, 1);
            const float s1 = __shfl_xor_sync(0xffffffffu, odd ? d1 : d3, 1);
            const float zi = (odd ? s0 : d0) + bb.x;
            const float zf = (odd ? s1 : d1) + bb.y;
            const float zg = (odd ? d2 : s0) + bb.z;
            const float zo = (odd ? d3 : s1) + bb.w;
            const int row = m0 + wm * 32 + mi * 16 + g + (odd ? 8 : 0);
            const float ig = fsigm(zi);
            const float fg = fsigm(zf);
            const float gg = ftanh(zg);
            const float og = fsigm(zo);
            const size_t off = (size_t)u * BATCH + row;   // col-major
            const float cn = fg * cbuf[off] + ig * gg;
            cbuf[off] = cn;
            const float hv = og * ftanh(cn);
            const __half hh = __float2half_rn(hv);
            hdhi[off] = hh;
            hdlo[off] = __float2half_rn(hv - __half2float(hh));
        }
    }
}

__global__ __launch_bounds__(256, 3) void lstm1_first_kernel() {
    extern __shared__ char smem[];
    lstm_body<FEAT, H1, 48>(0, (blockIdx.x & 255) * 128, (blockIdx.x >> 8) * 128, smem);
}

// combined: lstm2(t) on blocks [0,256); lstm1(t+1) on blocks [256,1280)
__global__ __launch_bounds__(256, 3) void step_kernel(int t, int do_l1) {
    extern __shared__ char smem[];
    if (blockIdx.x < 256) {
        lstm_body<H1, H2, 32>(t, blockIdx.x * 128, 0, smem);
    } else if (do_l1) {
        const int bx = blockIdx.x - 256;
        lstm_body<FEAT, H1, 48>(t + 1, (bx & 255) * 128, (bx >> 8) * 128, smem);
    }
}

// ---------------- init & prepack ----------------
__global__ void init_state_kernel() {
    int idx = blockIdx.x * blockDim.x + threadIdx.x;
    int stride = gridDim.x * blockDim.x;
    const __half z = __float2half(0.f);
    for (int i = idx; i < BATCH * H1; i += stride) {
        g_h1hi[0][i] = z; g_h1lo[0][i] = z; g_c1[i] = 0.f;
    }
    for (int i = idx; i < BATCH * H2; i += stride) {
        g_h2hi[0][i] = z; g_h2lo[0][i] = z; g_c2[i] = 0.f;
    }
}

__global__ void prepack_kernel(const float* __restrict__ Wx1, const float* __restrict__ Wh1,
                               const float* __restrict__ b1,
                               const float* __restrict__ Wx2, const float* __restrict__ Wh2,
                               const float* __restrict__ b2,
                               const float* __restrict__ W_d1, const float* __restrict__ b_d1,
                               const float* __restrict__ gamma, const float* __restrict__ beta,
                               const float* __restrict__ mean, const float* __restrict__ var) {
    int idx = blockIdx.x * blockDim.x + threadIdx.x;
    int stride = gridDim.x * blockDim.x;
    {
        constexpr int K = FEAT + H1;
        for (int i = idx; i < 4 * H1 * K; i += stride) {
            int n = i / K, k = i % K;
            int u = n >> 2, g = n & 3, src = g * H1 + u;
            float w = (k < FEAT) ? Wx1[k * 4 * H1 + src] : Wh1[(k - FEAT) * 4 * H1 + src];
            g_Wp1[(size_t)n * K + k] = __float2half_rn(w);
        }
        for (int i = idx; i < 4 * H1; i += stride) {
            int u = i >> 2, g = i & 3;
            g_bc1[i] = b1[g * H1 + u];
        }
    }
    {
        constexpr int K = H1 + H2;
        for (int i = idx; i < 4 * H2 * K; i += stride) {
            int n = i / K, k = i % K;
            int u = n >> 2, g = n & 3, src = g * H2 + u;
            float w = (k < H1) ? Wx2[k * 4 * H2 + src] : Wh2[(k - H1) * 4 * H2 + src];
            g_Wp2[(size_t)n * K + k] = __float2half_rn(w);
        }
        for (int i = idx; i < 4 * H2; i += stride) {
            int u = i >> 2, g = i & 3;
            g_bc2[i] = b2[g * H2 + u];
        }
    }
    // Dense1 weights: bf16 hi/lo panel-major (verified)
    for (int i = idx; i < D_DENSE * D_IN; i += stride) {
        int n = i / D_IN, k = i % D_IN;
        int p = k >> 7, kk = k & 127;
        float w = W_d1[(size_t)k * D_DENSE + n];
        __nv_bfloat16 hi = __float2bfloat16(w);
        g_WpD[(size_t)n * 1024 + p * 256 + kk] = hi;
        g_WpD[(size_t)n * 1024 + p * 256 + 128 + kk] = __float2bfloat16(w - __bfloat162float(hi));
    }
    for (int i = idx; i < D_DENSE; i += stride) {
        float sc = gamma[i] * rsqrtf(var[i] + 1e-3f);
        g_d1sc[i] = sc;
        g_d1sh[i] = beta[i] + (b_d1[i] - mean[i]) * sc;
    }
}

// ---------------- Dense1 (verified bf16 3-term engine), act written col-major fp16 ---------
template <int K, int S>
__device__ __forceinline__ void warp_gemm3(uint32_t Asm, uint32_t Bsm,
                                           int wm, int wn, int lane, float acc[2][8][4]) {
    const uint32_t abase = Asm + ((((uint32_t)(wm * 32 + (lane & 15))) * S + ((lane >> 4) << 3)) << 1);
    const uint32_t bbase = Bsm + ((((uint32_t)(wn * 64 + ((lane >> 4) << 3) + (lane & 7))) * S
                                   + (((lane >> 3) & 1) << 3)) << 1);
#pragma unroll
    for (int term = 0; term < 3; term++) {
        const int ao = (term == 1) ? K : 0;
        const int bo = (term == 2) ? K : 0;
#pragma unroll
        for (int c = 0; c < K / 16; c++) {
            uint32_t a0[4], a1[4], b[4][4];
            ldsm4(a0, abase + ((ao + c * 16) << 1));
            ldsm4(a1, abase + ((16 * S + ao + c * 16) << 1));
#pragma unroll
            for (int nj = 0; nj < 4; nj++)
                ldsm4(b[nj], bbase + (((nj * 16) * S + bo + c * 16) << 1));
#pragma unroll
            for (int mi = 0; mi < 2; mi++) {
                const uint32_t* A = mi ? a1 : a0;
#pragma unroll
                for (int nj = 0; nj < 4; nj++) {
                    mma16816bf(acc[mi][2 * nj], A, b[nj][0], b[nj][1]);
                    mma16816bf(acc[mi][2 * nj + 1], A, b[nj][2], b[nj][3]);
                }
            }
        }
    }
}

__global__ __launch_bounds__(256, 1) void dense1_kernel(const float* __restrict__ x) {
    constexpr int KP = 128;
    constexpr int S = 2 * KP + 8;    // 264
    extern __shared__ char smem[];
    const uint32_t Asm = smem_u32(smem);
    const uint32_t Bsm = Asm + 128 * S * 2;
    char* const Bc = smem + 128 * S * 2;
    const int tid = threadIdx.x;
    const int lane = tid & 31, wid = tid >> 5;
    const int wm = wid & 3, wn = wid >> 2;
    const int m0 = blockIdx.x * 128, n0 = blockIdx.y * 128;

    float acc[2][8][4] = {};
    for (int p = 0; p < 4; p++) {
        for (int task = tid; task < 128 * 16; task += 256) {
            const int r = task >> 4, o = task & 15;
            const float* src = x + (size_t)(m0 + r) * D_IN + p * KP + o * 8;
            const float4 v0 = *(const float4*)src;
            const float4 v1 = *(const float4*)(src + 4);
            __nv_bfloat16 h[8], l[8];
            const float vv[8] = {v0.x, v0.y, v0.z, v0.w, v1.x, v1.y, v1.z, v1.w};
#pragma unroll
            for (int i = 0; i < 8; i++) {
                h[i] = __float2bfloat16(vv[i]);
                l[i] = __float2bfloat16(vv[i] - __bfloat162float(h[i]));
            }
            *(uint4*)(smem + ((size_t)r * S + o * 8) * 2) = *(uint4*)h;
            *(uint4*)(smem + ((size_t)r * S + KP + o * 8) * 2) = *(uint4*)l;
        }
        for (int task = tid; task < 128 * 32; task += 256) {
            const int n = task >> 5, o = task & 31;
            const uint4 v = *(const uint4*)(g_WpD + (size_t)(n0 + n) * 1024 + p * 256 + o * 8);
            *(uint4*)(Bc + ((size_t)n * S + o * 8) * 2) = v;
        }
        __syncthreads();
        warp_gemm3<KP, S>(Asm, Bsm, wm, wn, lane, acc);
        __syncthreads();
    }

    const int g = lane >> 2;
#pragma unroll
    for (int ni = 0; ni < 8; ni++) {
        const int n = n0 + wn * 64 + ni * 8 + (lane & 3) * 2;
        const float sc0 = g_d1sc[n], sc1 = g_d1sc[n + 1];
        const float sh0 = g_d1sh[n], sh1 = g_d1sh[n + 1];
#pragma unroll
        for (int mi = 0; mi < 2; mi++) {
#pragma unroll
            for (int half = 0; half < 2; half++) {
                const int row = m0 + wm * 32 + mi * 16 + g + half * 8;
                float v0 = acc[mi][ni][half * 2 + 0] * sc0 + sh0;
                float v1 = acc[mi][ni][half * 2 + 1] * sc1 + sh1;
                v0 = (v0 >= 0.f) ? v0 : 0.2f * v0;
                v1 = (v1 >= 0.f) ? v1 : 0.2f * v1;
                const __half h0 = __float2half_rn(v0), h1 = __float2half_rn(v1);
                g_acthi[(size_t)n * BATCH + row] = h0;
                g_acthi[(size_t)(n + 1) * BATCH + row] = h1;
                g_actlo[(size_t)n * BATCH + row] = __float2half_rn(v0 - __half2float(h0));
                g_actlo[(size_t)(n + 1) * BATCH + row] = __float2half_rn(v1 - __half2float(h1));
            }
        }
    }
}

// ---------------- Dense2 + softmax (col-major fp16 h2) ----------------
__global__ __launch_bounds__(256) void dense2_softmax_kernel(
    const float* __restrict__ Wd2, const float* __restrict__ bd2, float* __restrict__ out) {
    __shared__ float Ws[H2 * NCLS];
    __shared__ float bs[NCLS];
    int tid = threadIdx.x;
    for (int i = tid; i < H2 * NCLS; i += blockDim.x) Ws[i] = Wd2[i];
    if (tid < NCLS) bs[tid] = bd2[tid];
    __syncthreads();
    int row = blockIdx.x * blockDim.x + tid;
    const __half* hh = g_h2hi[0];  // t=15 writes buffer 0
    const __half* hl = g_h2lo[0];
    float acc[NCLS];
#pragma unroll
    for (int j = 0; j < NCLS; j++) acc[j] = bs[j];
#pragma unroll
    for (int k = 0; k < H2; k++) {
        float xv = __half2float(hh[(size_t)k * BATCH + row])
                 + __half2float(hl[(size_t)k * BATCH + row]);
#pragma unroll
        for (int j = 0; j < NCLS; j++) acc[j] += xv * Ws[k * NCLS + j];
    }
    float m = acc[0];
#pragma unroll
    for (int j = 1; j < NCLS; j++) m = fmaxf(m, acc[j]);
    float ssum = 0.f;
#pragma unroll
    for (int j = 0; j < NCLS; j++) { acc[j] = expf(acc[j] - m); ssum += acc[j]; }
    float inv = 1.f / ssum;
#pragma unroll
    for (int j = 0; j < NCLS; j++) out[(size_t)row * NCLS + j] = acc[j] * inv;
}

// ---------------- launch ----------------
extern "C" void kernel_launch(void* const* d_in, const int* in_sizes, int n_in,
                              void* d_out, int out_size) {
    const float* x        = (const float*)d_in[0];
    const float* W_d1     = (const float*)d_in[1];
    const float* b_d1     = (const float*)d_in[2];
    const float* bn_gamma = (const float*)d_in[3];
    const float* bn_beta  = (const float*)d_in[4];
    const float* bn_mean  = (const float*)d_in[5];
    const float* bn_var   = (const float*)d_in[6];
    const float* Wx1      = (const float*)d_in[7];
    const float* Wh1      = (const float*)d_in[8];
    const float* b1       = (const float*)d_in[9];
    const float* Wx2      = (const float*)d_in[10];
    const float* Wh2      = (const float*)d_in[11];
    const float* b2       = (const float*)d_in[12];
    const float* W_d2     = (const float*)d_in[13];
    const float* b_d2     = (const float*)d_in[14];
    float* out = (float*)d_out;

    // LSTM1: 2*(48*136*2) + 128*(144+8)*2 = 26112 + 38912 = 65024
    // LSTM2: 2*(32*136*2) + 128*(160+8)*2 = 17408 + 43008 = 60416
    const int SM_STEP = 65024;
    const int SMD     = 2 * 128 * (2 * 128 + 8) * 2;     // 135168

    cudaFuncSetAttribute(dense1_kernel, cudaFuncAttributeMaxDynamicSharedMemorySize, SMD);
    cudaFuncSetAttribute(lstm1_first_kernel, cudaFuncAttributeMaxDynamicSharedMemorySize, SM_STEP);
    cudaFuncSetAttribute(step_kernel, cudaFuncAttributeMaxDynamicSharedMemorySize, SM_STEP);

    prepack_kernel<<<256, 256>>>(Wx1, Wh1, b1, Wx2, Wh2, b2, W_d1, b_d1,
                                 bn_gamma, bn_beta, bn_mean, bn_var);
    init_state_kernel<<<2048, 256>>>();
    dense1_kernel<<<dim3(BATCH / 128, D_DENSE / 128), 256, SMD>>>(x);
    lstm1_first_kernel<<<1024, 256, SM_STEP>>>();
    for (int t = 0; t < TSTEPS; t++) {
        step_kernel<<<1280, 256, SM_STEP>>>(t, (t < TSTEPS - 1) ? 1 : 0);
    }
    dense2_softmax_kernel<<<BATCH / 256, 256>>>(W_d2, b_d2, out);
}

// round 10
// speedup vs baseline: 1.2629x; 1.2629x over previous
#include <cuda_runtime.h>
#include <cuda_bf16.h>
#include <cuda_fp16.h>
#include <math.h>
#include <stdint.h>

#define BATCH   32768
#define D_IN    512
#define D_DENSE 256
#define TSTEPS  16
#define FEAT    16
#define H1      128
#define H2      32
#define NCLS    10

// ---------------- state: COLUMN-major [feature][BATCH], fp16 hi/lo pairs ----------------
__device__ __half g_acthi[D_DENSE * BATCH], g_actlo[D_DENSE * BATCH];
__device__ __half g_h1hi[2][H1 * BATCH],    g_h1lo[2][H1 * BATCH];
__device__ __half g_h2hi[2][H2 * BATCH],    g_h2lo[2][H2 * BATCH];
__device__ float g_c1[H1 * BATCH], g_c2[H2 * BATCH];

// prepacked LSTM weights: single fp16, row n (gate-interleaved), K cols
__device__ __half g_Wp1[(4 * H1) * (FEAT + H1)];   // [512][144]
__device__ __half g_Wp2[(4 * H2) * (H1 + H2)];     // [128][160]
// dense1 weights stay bf16 3-term (verified engine)
__device__ __nv_bfloat16 g_WpD[D_DENSE * 2 * D_IN];  // [256][1024], panel-major
__device__ float g_bc1[4 * H1], g_bc2[4 * H2];
__device__ float g_d1sc[D_DENSE], g_d1sh[D_DENSE];

// ---------------- helpers ----------------
__device__ __forceinline__ uint32_t smem_u32(const void* p) {
    uint32_t a;
    asm("{ .reg .u64 t; cvta.to.shared.u64 t, %1; cvt.u32.u64 %0, t; }" : "=r"(a) : "l"(p));
    return a;
}
__device__ __forceinline__ float ftanh(float x) {
    float y;
    asm("tanh.approx.f32 %0, %1;" : "=f"(y) : "f"(x));
    return y;
}
__device__ __forceinline__ float fsigm(float x) { return 0.5f * ftanh(0.5f * x) + 0.5f; }

__device__ __forceinline__ void ldsm4(uint32_t* r, uint32_t addr) {
    asm volatile("ldmatrix.sync.aligned.m8n8.x4.shared.b16 {%0,%1,%2,%3}, [%4];"
                 : "=r"(r[0]), "=r"(r[1]), "=r"(r[2]), "=r"(r[3]) : "r"(addr));
}
__device__ __forceinline__ void ldsm4t(uint32_t* r, uint32_t addr) {
    asm volatile("ldmatrix.sync.aligned.m8n8.x4.trans.shared.b16 {%0,%1,%2,%3}, [%4];"
                 : "=r"(r[0]), "=r"(r[1]), "=r"(r[2]), "=r"(r[3]) : "r"(addr));
}
__device__ __forceinline__ void mma16816bf(float* d, const uint32_t* a, uint32_t b0, uint32_t b1) {
    asm volatile(
        "mma.sync.aligned.m16n8k16.row.col.f32.bf16.bf16.f32 "
        "{%0,%1,%2,%3}, {%4,%5,%6,%7}, {%8,%9}, {%0,%1,%2,%3};"
        : "+f"(d[0]), "+f"(d[1]), "+f"(d[2]), "+f"(d[3])
        : "r"(a[0]), "r"(a[1]), "r"(a[2]), "r"(a[3]), "r"(b0), "r"(b1));
}
__device__ __forceinline__ void mma16816h(float* d, const uint32_t* a, uint32_t b0, uint32_t b1) {
    asm volatile(
        "mma.sync.aligned.m16n8k16.row.col.f32.f16.f16.f32 "
        "{%0,%1,%2,%3}, {%4,%5,%6,%7}, {%8,%9}, {%0,%1,%2,%3};"
        : "+f"(d[0]), "+f"(d[1]), "+f"(d[2]), "+f"(d[3])
        : "r"(a[0]), "r"(a[1]), "r"(a[2]), "r"(a[3]), "r"(b0), "r"(b1));
}
__device__ __forceinline__ void cp16(uint32_t dst, const void* src) {
    asm volatile("cp.async.cg.shared.global [%0], [%1], 16;" :: "r"(dst), "l"(src));
}
#define CP_COMMIT() asm volatile("cp.async.commit_group;" ::: "memory")
#define CP_WAIT(n)  asm volatile("cp.async.wait_group %0;" :: "n"(n) : "memory")

// ===== fused LSTM step: fp16 2-term, FUSED hi/lo chunks, resident fp16 B, col-major state
// 256 threads, 8 warps 4(M)x2(N), warp tile 32x64, CTA tile 128x128.
template <int KX, int HID, int BK>
__device__ __forceinline__ void lstm_body(int t, int m0, int n0, char* smemc) {
    constexpr int K = KX + HID;
    constexpr int SROW = 136;                 // A smem: elems per k-row (272B, conflict-free)
    constexpr int STG_A = 2 * BK * SROW * 2;  // stage holds hi rows [0,BK) and lo rows [BK,2BK)
    constexpr int SB = K + 8;                 // B row length in halfs (stride/16B odd)
    constexpr int NCH = K / BK;               // fused chunks
    constexpr int GB = K / 8;
    const int tid = threadIdx.x;
    const int lane = tid & 31, wid = tid >> 5;
    const int wm = wid & 3, wn = wid >> 2;    // 4 x 2
    const uint32_t sbase = smem_u32(smemc);
    const uint32_t Bbase = sbase + 2 * STG_A;
    const int p = t & 1;

    const __half *xhi, *xlo, *hhi, *hlo;
    __half *hdhi, *hdlo;
    float* cbuf;
    const __half* W;
    const float* bias;
    int xoff;
    if (HID == H1) {
        xhi = g_acthi; xlo = g_actlo; xoff = t * FEAT;
        hhi = g_h1hi[p]; hlo = g_h1lo[p];
        hdhi = g_h1hi[p ^ 1]; hdlo = g_h1lo[p ^ 1];
        cbuf = g_c1; W = g_Wp1; bias = g_bc1;
    } else {
        xhi = g_h1hi[p ^ 1]; xlo = g_h1lo[p ^ 1]; xoff = 0;
        hhi = g_h2hi[p]; hlo = g_h2lo[p];
        hdhi = g_h2hi[p ^ 1]; hdlo = g_h2lo[p ^ 1];
        cbuf = g_c2; W = g_Wp2; bias = g_bc2;
    }

    // A loader: hi AND lo for k-range [c*BK, (c+1)*BK), 16B contiguous per (k, m-group)
    auto load_a = [&](int c) {
        const int kbase = c * BK;
        const uint32_t As = sbase + (uint32_t)(c & 1) * STG_A;
#pragma unroll
        for (int task = tid; task < 2 * BK * 16; task += 256) {
            const int kh = task >> 4, mg = task & 15;
            const bool lo = kh >= BK;
            const int k = lo ? kh - BK : kh;
            const int col = kbase + k;
            const __half* src = (col < KX)
                ? (lo ? xlo : xhi) + (size_t)(xoff + col) * BATCH + m0 + mg * 8
                : (lo ? hlo : hhi) + (size_t)(col - KX) * BATCH + m0 + mg * 8;
            cp16(As + (uint32_t)(kh * SROW + mg * 8) * 2, src);
        }
    };

    // prologue: resident B (single fp16) + first fused A chunk
#pragma unroll
    for (int task = tid; task < 128 * GB; task += 256) {
        const int n = task / GB, gg = task % GB;
        cp16(Bbase + (uint32_t)(n * SB + gg * 8) * 2,
             W + (size_t)(n0 + n) * K + gg * 8);
    }
    load_a(0);
    CP_COMMIT();

    const uint32_t arow = (uint32_t)((lane & 7) + ((lane >> 4) << 3));
    const uint32_t acol = (uint32_t)(wm * 32 + (((lane >> 3) & 1) << 3));
    const uint32_t brow = (uint32_t)(wn * 64 + ((lane >> 4) << 3) + (lane & 7));
    const uint32_t bcol8 = (uint32_t)(((lane >> 3) & 1) << 3);
    float acc[2][8][4] = {};

#pragma unroll 1
    for (int c = 0; c < NCH; c++) {
        CP_WAIT(0);
        __syncthreads();
        if (c + 1 < NCH) { load_a(c + 1); CP_COMMIT(); }
        const int kbase = c * BK;
        const uint32_t As = sbase + (uint32_t)(c & 1) * STG_A;
#pragma unroll
        for (int kk = 0; kk < BK / 16; kk++) {
            uint32_t ah0[4], ah1[4], al0[4], al1[4];
            const uint32_t hrow = kk * 16 + arow;
            ldsm4t(ah0, As + (hrow * SROW + acol) * 2);
            ldsm4t(ah1, As + (hrow * SROW + acol + 16) * 2);
            ldsm4t(al0, As + ((BK + hrow) * SROW + acol) * 2);
            ldsm4t(al1, As + ((BK + hrow) * SROW + acol + 16) * 2);
            const uint32_t cofs = (uint32_t)(kbase + kk * 16) + bcol8;
#pragma unroll
            for (int nj = 0; nj < 4; nj++) {
                uint32_t b[4];
                ldsm4(b, Bbase + ((brow + nj * 16) * SB + cofs) * 2);
                mma16816h(acc[0][2 * nj], ah0, b[0], b[1]);
                mma16816h(acc[0][2 * nj + 1], ah0, b[2], b[3]);
                mma16816h(acc[1][2 * nj], ah1, b[0], b[1]);
                mma16816h(acc[1][2 * nj + 1], ah1, b[2], b[3]);
                mma16816h(acc[0][2 * nj], al0, b[0], b[1]);
                mma16816h(acc[0][2 * nj + 1], al0, b[2], b[3]);
                mma16816h(acc[1][2 * nj], al1, b[0], b[1]);
                mma16816h(acc[1][2 * nj + 1], al1, b[2], b[3]);
            }
        }
    }

    // epilogue: pair-swap gates; col-major state -> coalesced stores
    const int g = lane >> 2;
    const bool odd = lane & 1;
#pragma unroll
    for (int ni = 0; ni < 8; ni++) {
        const int u = ((n0 + wn * 64 + ni * 8) >> 2) + ((lane & 2) >> 1);
        const float4 bb = *(const float4*)(bias + 4 * u);
#pragma unroll
        for (int mi = 0; mi < 2; mi++) {
            const float d0 = acc[mi][ni][0], d1 = acc[mi][ni][1];
            const float d2 = acc[mi][ni][2], d3 = acc[mi][ni][3];
            const float s0 = __shfl_xor_sync(0xffffffffu, odd ? d0 : d2, 1);
            const float s1 = __shfl_xor_sync(0xffffffffu, odd ? d1 : d3, 1);
            const float zi = (odd ? s0 : d0) + bb.x;
            const float zf = (odd ? s1 : d1) + bb.y;
            const float zg = (odd ? d2 : s0) + bb.z;
            const float zo = (odd ? d3 : s1) + bb.w;
            const int row = m0 + wm * 32 + mi * 16 + g + (odd ? 8 : 0);
            const float ig = fsigm(zi);
            const float fg = fsigm(zf);
            const float gg = ftanh(zg);
            const float og = fsigm(zo);
            const size_t off = (size_t)u * BATCH + row;   // col-major
            const float cn = fg * cbuf[off] + ig * gg;
            cbuf[off] = cn;
            const float hv = og * ftanh(cn);
            const __half hh = __float2half_rn(hv);
            hdhi[off] = hh;
            hdlo[off] = __float2half_rn(hv - __half2float(hh));
        }
    }
}

__global__ __launch_bounds__(256, 2) void lstm1_first_kernel() {
    extern __shared__ char smem[];
    lstm_body<FEAT, H1, 48>(0, (blockIdx.x & 255) * 128, (blockIdx.x >> 8) * 128, smem);
}

// combined: lstm2(t) on blocks [0,256); lstm1(t+1) on blocks [256,1280)
__global__ __launch_bounds__(256, 2) void step_kernel(int t, int do_l1) {
    extern __shared__ char smem[];
    if (blockIdx.x < 256) {
        lstm_body<H1, H2, 32>(t, blockIdx.x * 128, 0, smem);
    } else if (do_l1) {
        const int bx = blockIdx.x - 256;
        lstm_body<FEAT, H1, 48>(t + 1, (bx & 255) * 128, (bx >> 8) * 128, smem);
    }
}

// ---------------- init & prepack ----------------
__global__ void init_state_kernel() {
    int idx = blockIdx.x * blockDim.x + threadIdx.x;
    int stride = gridDim.x * blockDim.x;
    const __half z = __float2half(0.f);
    for (int i = idx; i < BATCH * H1; i += stride) {
        g_h1hi[0][i] = z; g_h1lo[0][i] = z; g_c1[i] = 0.f;
    }
    for (int i = idx; i < BATCH * H2; i += stride) {
        g_h2hi[0][i] = z; g_h2lo[0][i] = z; g_c2[i] = 0.f;
    }
}

__global__ void prepack_kernel(const float* __restrict__ Wx1, const float* __restrict__ Wh1,
                               const float* __restrict__ b1,
                               const float* __restrict__ Wx2, const float* __restrict__ Wh2,
                               const float* __restrict__ b2,
                               const float* __restrict__ W_d1, const float* __restrict__ b_d1,
                               const float* __restrict__ gamma, const float* __restrict__ beta,
                               const float* __restrict__ mean, const float* __restrict__ var) {
    int idx = blockIdx.x * blockDim.x + threadIdx.x;
    int stride = gridDim.x * blockDim.x;
    {
        constexpr int K = FEAT + H1;
        for (int i = idx; i < 4 * H1 * K; i += stride) {
            int n = i / K, k = i % K;
            int u = n >> 2, g = n & 3, src = g * H1 + u;
            float w = (k < FEAT) ? Wx1[k * 4 * H1 + src] : Wh1[(k - FEAT) * 4 * H1 + src];
            g_Wp1[(size_t)n * K + k] = __float2half_rn(w);
        }
        for (int i = idx; i < 4 * H1; i += stride) {
            int u = i >> 2, g = i & 3;
            g_bc1[i] = b1[g * H1 + u];
        }
    }
    {
        constexpr int K = H1 + H2;
        for (int i = idx; i < 4 * H2 * K; i += stride) {
            int n = i / K, k = i % K;
            int u = n >> 2, g = n & 3, src = g * H2 + u;
            float w = (k < H1) ? Wx2[k * 4 * H2 + src] : Wh2[(k - H1) * 4 * H2 + src];
            g_Wp2[(size_t)n * K + k] = __float2half_rn(w);
        }
        for (int i = idx; i < 4 * H2; i += stride) {
            int u = i >> 2, g = i & 3;
            g_bc2[i] = b2[g * H2 + u];
        }
    }
    // Dense1 weights: bf16 hi/lo panel-major (verified)
    for (int i = idx; i < D_DENSE * D_IN; i += stride) {
        int n = i / D_IN, k = i % D_IN;
        int p = k >> 7, kk = k & 127;
        float w = W_d1[(size_t)k * D_DENSE + n];
        __nv_bfloat16 hi = __float2bfloat16(w);
        g_WpD[(size_t)n * 1024 + p * 256 + kk] = hi;
        g_WpD[(size_t)n * 1024 + p * 256 + 128 + kk] = __float2bfloat16(w - __bfloat162float(hi));
    }
    for (int i = idx; i < D_DENSE; i += stride) {
        float sc = gamma[i] * rsqrtf(var[i] + 1e-3f);
        g_d1sc[i] = sc;
        g_d1sh[i] = beta[i] + (b_d1[i] - mean[i]) * sc;
    }
}

// ---------------- Dense1 (verified bf16 3-term engine), act written col-major fp16 ---------
template <int K, int S>
__device__ __forceinline__ void warp_gemm3(uint32_t Asm, uint32_t Bsm,
                                           int wm, int wn, int lane, float acc[2][8][4]) {
    const uint32_t abase = Asm + ((((uint32_t)(wm * 32 + (lane & 15))) * S + ((lane >> 4) << 3)) << 1);
    const uint32_t bbase = Bsm + ((((uint32_t)(wn * 64 + ((lane >> 4) << 3) + (lane & 7))) * S
                                   + (((lane >> 3) & 1) << 3)) << 1);
#pragma unroll
    for (int term = 0; term < 3; term++) {
        const int ao = (term == 1) ? K : 0;
        const int bo = (term == 2) ? K : 0;
#pragma unroll
        for (int c = 0; c < K / 16; c++) {
            uint32_t a0[4], a1[4], b[4][4];
            ldsm4(a0, abase + ((ao + c * 16) << 1));
            ldsm4(a1, abase + ((16 * S + ao + c * 16) << 1));
#pragma unroll
            for (int nj = 0; nj < 4; nj++)
                ldsm4(b[nj], bbase + (((nj * 16) * S + bo + c * 16) << 1));
#pragma unroll
            for (int mi = 0; mi < 2; mi++) {
                const uint32_t* A = mi ? a1 : a0;
#pragma unroll
                for (int nj = 0; nj < 4; nj++) {
                    mma16816bf(acc[mi][2 * nj], A, b[nj][0], b[nj][1]);
                    mma16816bf(acc[mi][2 * nj + 1], A, b[nj][2], b[nj][3]);
                }
            }
        }
    }
}

__global__ __launch_bounds__(256, 1) void dense1_kernel(const float* __restrict__ x) {
    constexpr int KP = 128;
    constexpr int S = 2 * KP + 8;    // 264
    extern __shared__ char smem[];
    const uint32_t Asm = smem_u32(smem);
    const uint32_t Bsm = Asm + 128 * S * 2;
    char* const Bc = smem + 128 * S * 2;
    const int tid = threadIdx.x;
    const int lane = tid & 31, wid = tid >> 5;
    const int wm = wid & 3, wn = wid >> 2;
    const int m0 = blockIdx.x * 128, n0 = blockIdx.y * 128;

    float acc[2][8][4] = {};
    for (int p = 0; p < 4; p++) {
        for (int task = tid; task < 128 * 16; task += 256) {
            const int r = task >> 4, o = task & 15;
            const float* src = x + (size_t)(m0 + r) * D_IN + p * KP + o * 8;
            const float4 v0 = *(const float4*)src;
            const float4 v1 = *(const float4*)(src + 4);
            __nv_bfloat16 h[8], l[8];
            const float vv[8] = {v0.x, v0.y, v0.z, v0.w, v1.x, v1.y, v1.z, v1.w};
#pragma unroll
            for (int i = 0; i < 8; i++) {
                h[i] = __float2bfloat16(vv[i]);
                l[i] = __float2bfloat16(vv[i] - __bfloat162float(h[i]));
            }
            *(uint4*)(smem + ((size_t)r * S + o * 8) * 2) = *(uint4*)h;
            *(uint4*)(smem + ((size_t)r * S + KP + o * 8) * 2) = *(uint4*)l;
        }
        for (int task = tid; task < 128 * 32; task += 256) {
            const int n = task >> 5, o = task & 31;
            const uint4 v = *(const uint4*)(g_WpD + (size_t)(n0 + n) * 1024 + p * 256 + o * 8);
            *(uint4*)(Bc + ((size_t)n * S + o * 8) * 2) = v;
        }
        __syncthreads();
        warp_gemm3<KP, S>(Asm, Bsm, wm, wn, lane, acc);
        __syncthreads();
    }

    const int g = lane >> 2;
#pragma unroll
    for (int ni = 0; ni < 8; ni++) {
        const int n = n0 + wn * 64 + ni * 8 + (lane & 3) * 2;
        const float sc0 = g_d1sc[n], sc1 = g_d1sc[n + 1];
        const float sh0 = g_d1sh[n], sh1 = g_d1sh[n + 1];
#pragma unroll
        for (int mi = 0; mi < 2; mi++) {
#pragma unroll
            for (int half = 0; half < 2; half++) {
                const int row = m0 + wm * 32 + mi * 16 + g + half * 8;
                float v0 = acc[mi][ni][half * 2 + 0] * sc0 + sh0;
                float v1 = acc[mi][ni][half * 2 + 1] * sc1 + sh1;
                v0 = (v0 >= 0.f) ? v0 : 0.2f * v0;
                v1 = (v1 >= 0.f) ? v1 : 0.2f * v1;
                const __half h0 = __float2half_rn(v0), h1 = __float2half_rn(v1);
                g_acthi[(size_t)n * BATCH + row] = h0;
                g_acthi[(size_t)(n + 1) * BATCH + row] = h1;
                g_actlo[(size_t)n * BATCH + row] = __float2half_rn(v0 - __half2float(h0));
                g_actlo[(size_t)(n + 1) * BATCH + row] = __float2half_rn(v1 - __half2float(h1));
            }
        }
    }
}

// ---------------- Dense2 + softmax (col-major fp16 h2) ----------------
__global__ __launch_bounds__(256) void dense2_softmax_kernel(
    const float* __restrict__ Wd2, const float* __restrict__ bd2, float* __restrict__ out) {
    __shared__ float Ws[H2 * NCLS];
    __shared__ float bs[NCLS];
    int tid = threadIdx.x;
    for (int i = tid; i < H2 * NCLS; i += blockDim.x) Ws[i] = Wd2[i];
    if (tid < NCLS) bs[tid] = bd2[tid];
    __syncthreads();
    int row = blockIdx.x * blockDim.x + tid;
    const __half* hh = g_h2hi[0];  // t=15 writes buffer 0
    const __half* hl = g_h2lo[0];
    float acc[NCLS];
#pragma unroll
    for (int j = 0; j < NCLS; j++) acc[j] = bs[j];
#pragma unroll
    for (int k = 0; k < H2; k++) {
        float xv = __half2float(hh[(size_t)k * BATCH + row])
                 + __half2float(hl[(size_t)k * BATCH + row]);
#pragma unroll
        for (int j = 0; j < NCLS; j++) acc[j] += xv * Ws[k * NCLS + j];
    }
    float m = acc[0];
#pragma unroll
    for (int j = 1; j < NCLS; j++) m = fmaxf(m, acc[j]);
    float ssum = 0.f;
#pragma unroll
    for (int j = 0; j < NCLS; j++) { acc[j] = expf(acc[j] - m); ssum += acc[j]; }
    float inv = 1.f / ssum;
#pragma unroll
    for (int j = 0; j < NCLS; j++) out[(size_t)row * NCLS + j] = acc[j] * inv;
}

// ---------------- launch ----------------
extern "C" void kernel_launch(void* const* d_in, const int* in_sizes, int n_in,
                              void* d_out, int out_size) {
    const float* x        = (const float*)d_in[0];
    const float* W_d1     = (const float*)d_in[1];
    const float* b_d1     = (const float*)d_in[2];
    const float* bn_gamma = (const float*)d_in[3];
    const float* bn_beta  = (const float*)d_in[4];
    const float* bn_mean  = (const float*)d_in[5];
    const float* bn_var   = (const float*)d_in[6];
    const float* Wx1      = (const float*)d_in[7];
    const float* Wh1      = (const float*)d_in[8];
    const float* b1       = (const float*)d_in[9];
    const float* Wx2      = (const float*)d_in[10];
    const float* Wh2      = (const float*)d_in[11];
    const float* b2       = (const float*)d_in[12];
    const float* W_d2     = (const float*)d_in[13];
    const float* b_d2     = (const float*)d_in[14];
    float* out = (float*)d_out;

    // LSTM1: 2*(2*48*136*2) + 128*(144+8)*2 = 52224 + 38912 = 91136
    // LSTM2: 2*(2*32*136*2) + 128*(160+8)*2 = 34816 + 43008 = 77824
    const int SM_STEP = 91136;
    const int SMD     = 2 * 128 * (2 * 128 + 8) * 2;     // 135168

    cudaFuncSetAttribute(dense1_kernel, cudaFuncAttributeMaxDynamicSharedMemorySize, SMD);
    cudaFuncSetAttribute(lstm1_first_kernel, cudaFuncAttributeMaxDynamicSharedMemorySize, SM_STEP);
    cudaFuncSetAttribute(step_kernel, cudaFuncAttributeMaxDynamicSharedMemorySize, SM_STEP);

    prepack_kernel<<<256, 256>>>(Wx1, Wh1, b1, Wx2, Wh2, b2, W_d1, b_d1,
                                 bn_gamma, bn_beta, bn_mean, bn_var);
    init_state_kernel<<<2048, 256>>>();
    dense1_kernel<<<dim3(BATCH / 128, D_DENSE / 128), 256, SMD>>>(x);
    lstm1_first_kernel<<<1024, 256, SM_STEP>>>();
    for (int t = 0; t < TSTEPS; t++) {
        step_kernel<<<1280, 256, SM_STEP>>>(t, (t < TSTEPS - 1) ? 1 : 0);
    }
    dense2_softmax_kernel<<<BATCH / 256, 256>>>(W_d2, b_d2, out);
}